// round 6
// baseline (speedup 1.0000x reference)
#include <cuda_runtime.h>
#include <cstdint>

#define T_SEQ 16384
#define IN_DIM 512
#define H_DIM  1024
#define G3     3072   // 3*H

// ---------------- scratch (static __device__, no allocations) ----------------
__device__ float g_gx[(size_t)T_SEQ * G3];          // 192 MiB, reused for both layers
__device__ float g_h1[(size_t)T_SEQ * H_DIM];       // 64 MiB
__device__ float g_h2[(size_t)T_SEQ * H_DIM];       // 64 MiB
__device__ unsigned long long g_hbuf[2][H_DIM];     // tagged h exchange (parity double-buffered)
__device__ float g_mu[H_DIM];
__device__ float g_rs[H_DIM];                       // rsqrt(var+eps)
__device__ float g_c[H_DIM];                        // fused BN*fc coefficient
__device__ float g_off[1];

// packed f32x2 FMA: d = a*b + d (per 32-bit half). Only reachable via PTX.
__device__ __forceinline__ void ffma2(unsigned long long& d,
                                      unsigned long long a,
                                      unsigned long long b) {
    asm("fma.rn.f32x2 %0, %1, %2, %0;" : "+l"(d) : "l"(a), "l"(b));
}
__device__ __forceinline__ float hsum2(unsigned long long v) {
    float2 f = *reinterpret_cast<float2*>(&v);
    return f.x + f.y;
}

// ---------------- init: reset tag buffers (needed per launch for graph replay) ----
__global__ void k_init() {
    int i = blockIdx.x * blockDim.x + threadIdx.x;
    if (i < 2 * H_DIM) ((unsigned long long*)g_hbuf)[i] = 0ull;
}

// ---------------- GEMM: C[M,3072] = A[M,K] @ W[3072,K]^T + bias ----------------
template<int K, int LAYER>
__global__ __launch_bounds__(256) void k_gemm(const float* __restrict__ Ain,
                                              const float* __restrict__ W,
                                              const float* __restrict__ bias) {
    const float* A = (LAYER == 0) ? Ain : g_h1;
    float* C = g_gx;
    __shared__ float As[16][128];
    __shared__ float Bs[16][128];
    const int tid = threadIdx.x;
    const int bm = blockIdx.y * 128;
    const int bn = blockIdx.x * 128;
    const int tx = tid & 15, ty = tid >> 4;

    float acc[8][8];
#pragma unroll
    for (int i = 0; i < 8; i++)
#pragma unroll
        for (int j = 0; j < 8; j++) acc[i][j] = 0.f;

    for (int k0 = 0; k0 < K; k0 += 16) {
#pragma unroll
        for (int i = 0; i < 2; i++) {
            int f = tid + i * 256;
            int m = f >> 2;
            int kq = (f & 3) << 2;
            float4 va = *(const float4*)(A + (size_t)(bm + m) * K + k0 + kq);
            As[kq + 0][m] = va.x; As[kq + 1][m] = va.y;
            As[kq + 2][m] = va.z; As[kq + 3][m] = va.w;
            float4 vb = *(const float4*)(W + (size_t)(bn + m) * K + k0 + kq);
            Bs[kq + 0][m] = vb.x; Bs[kq + 1][m] = vb.y;
            Bs[kq + 2][m] = vb.z; Bs[kq + 3][m] = vb.w;
        }
        __syncthreads();
#pragma unroll
        for (int kk = 0; kk < 16; kk++) {
            float a[8], b[8];
            *(float4*)(a)     = *(const float4*)&As[kk][ty * 8];
            *(float4*)(a + 4) = *(const float4*)&As[kk][ty * 8 + 4];
            *(float4*)(b)     = *(const float4*)&Bs[kk][tx * 8];
            *(float4*)(b + 4) = *(const float4*)&Bs[kk][tx * 8 + 4];
#pragma unroll
            for (int i = 0; i < 8; i++)
#pragma unroll
                for (int j = 0; j < 8; j++)
                    acc[i][j] = fmaf(a[i], b[j], acc[i][j]);
        }
        __syncthreads();
    }
#pragma unroll
    for (int i = 0; i < 8; i++) {
        int m = bm + ty * 8 + i;
#pragma unroll
        for (int j = 0; j < 8; j += 4) {
            int n = bn + tx * 8 + j;
            float4 o;
            o.x = acc[i][j + 0] + bias[n + 0];
            o.y = acc[i][j + 1] + bias[n + 1];
            o.z = acc[i][j + 2] + bias[n + 2];
            o.w = acc[i][j + 3] + bias[n + 3];
            *(float4*)(C + (size_t)m * G3 + n) = o;
        }
    }
}

// ---------------- persistent GRU recurrence ----------------
// R2-PROVEN sync skeleton (two __syncthreads per step, single hs buffer) with
// compute-side upgrades only:
//  - poll issues all 4 ld.relaxed.gpu.b64 before any tag check (MLP=4, one L2 RTT)
//  - lane owns interleaved float2 columns {2*lane+64*k}: conflict-free LDS.64,
//    coalesced weight loads, packed fma.rn.f32x2 (48 FFMA2 vs 96 FFMA)
//  - lane 0 publishes h_new before h_out store / gx prefetch (critical path first)
// 128 CTAs <= 148 SMs, 1 CTA/SM by reg+smem budget -> all co-resident.
// Tag protocol bounds CTA skew to 1 step; parity buffers never overwritten live.
__global__ __launch_bounds__(256, 1) void k_gru(const float* __restrict__ w_hh,
                                                const float* __restrict__ b_hh,
                                                float* __restrict__ h_out) {
    __shared__ float hs[H_DIM];
    const int tid  = threadIdx.x;
    const int warp = tid >> 5;
    const int lane = tid & 31;
    const int j = blockIdx.x * 8 + warp;

    // Packed recurrent weights: wX2[k] = {w[2*lane+64k], w[2*lane+64k+1]}
    unsigned long long wr2[16], wz2[16], wn2[16];
    {
        const float* pr = w_hh + (size_t)j * H_DIM + 2 * lane;
        const float* pz = w_hh + (size_t)(H_DIM + j) * H_DIM + 2 * lane;
        const float* pn = w_hh + (size_t)(2 * H_DIM + j) * H_DIM + 2 * lane;
#pragma unroll
        for (int k = 0; k < 16; k++) {
            wr2[k] = *(const unsigned long long*)(pr + 64 * k);
            wz2[k] = *(const unsigned long long*)(pz + 64 * k);
            wn2[k] = *(const unsigned long long*)(pn + 64 * k);
        }
    }
    float bhr = 0.f, bhz = 0.f, bhn = 0.f;
    float gxr = 0.f, gxz = 0.f, gxn = 0.f;
    if (lane == 0) {
        bhr = b_hh[j]; bhz = b_hh[H_DIM + j]; bhn = b_hh[2 * H_DIM + j];
        gxr = __ldg(&g_gx[j]);
        gxz = __ldg(&g_gx[H_DIM + j]);
        gxn = __ldg(&g_gx[2 * H_DIM + j]);
    }

    const int s0 = tid * 4;   // this thread stages slots s0..s0+3

    for (int t = 0; t < T_SEQ; t++) {
        // ---- poll tagged h of step t (tag == t); all 4 loads in flight per round ----
        {
            const unsigned long long* buf = g_hbuf[t & 1] + s0;
            const unsigned tag = (unsigned)t;
            unsigned long long u0, u1, u2, u3;
            for (;;) {
                asm volatile("ld.relaxed.gpu.b64 %0, [%1];" : "=l"(u0) : "l"(buf + 0) : "memory");
                asm volatile("ld.relaxed.gpu.b64 %0, [%1];" : "=l"(u1) : "l"(buf + 1) : "memory");
                asm volatile("ld.relaxed.gpu.b64 %0, [%1];" : "=l"(u2) : "l"(buf + 2) : "memory");
                asm volatile("ld.relaxed.gpu.b64 %0, [%1];" : "=l"(u3) : "l"(buf + 3) : "memory");
                bool ok = ((unsigned)(u0 >> 32) == tag) & ((unsigned)(u1 >> 32) == tag) &
                          ((unsigned)(u2 >> 32) == tag) & ((unsigned)(u3 >> 32) == tag);
                if (ok) break;
            }
            hs[s0 + 0] = __uint_as_float((unsigned)u0);
            hs[s0 + 1] = __uint_as_float((unsigned)u1);
            hs[s0 + 2] = __uint_as_float((unsigned)u2);
            hs[s0 + 3] = __uint_as_float((unsigned)u3);
        }
        __syncthreads();

        // ---- packed dot products: 16 float2 per gate per lane ----
        unsigned long long aR2 = 0ull, aZ2 = 0ull, aN2 = 0ull;
        const unsigned long long* hp = (const unsigned long long*)hs;
#pragma unroll
        for (int k = 0; k < 16; k++) {
            unsigned long long h2 = hp[lane + 32 * k];
            ffma2(aR2, wr2[k], h2);
            ffma2(aZ2, wz2[k], h2);
            ffma2(aN2, wn2[k], h2);
        }
        float aR = hsum2(aR2), aZ = hsum2(aZ2), aN = hsum2(aN2);
#pragma unroll
        for (int off = 16; off > 0; off >>= 1) {
            aR += __shfl_xor_sync(0xffffffffu, aR, off);
            aZ += __shfl_xor_sync(0xffffffffu, aZ, off);
            aN += __shfl_xor_sync(0xffffffffu, aN, off);
        }

        if (lane == 0) {
            float r = 1.f / (1.f + __expf(-(gxr + aR + bhr)));
            float z = 1.f / (1.f + __expf(-(gxz + aZ + bhz)));
            float npre = gxn + r * (aN + bhn);
            npre = fminf(fmaxf(npre, -20.f), 20.f);
            float e = __expf(-2.f * npre);
            float n = (1.f - e) / (1.f + e);
            float hprev = hs[j];
            float hnew = (1.f - z) * n + z * hprev;

            // publish FIRST (cross-SM critical path), then bookkeeping
            unsigned long long pk =
                ((unsigned long long)(unsigned)(t + 1) << 32) | (unsigned long long)__float_as_uint(hnew);
            asm volatile("st.relaxed.gpu.b64 [%0], %1;"
                         :: "l"(&g_hbuf[(t + 1) & 1][j]), "l"(pk) : "memory");

            h_out[(size_t)t * H_DIM + j] = hnew;

            int tn = (t + 1 < T_SEQ) ? (t + 1) : t;
            const float* gp = g_gx + (size_t)tn * G3;
            gxr = __ldg(gp + j);
            gxz = __ldg(gp + H_DIM + j);
            gxn = __ldg(gp + 2 * H_DIM + j);
        }
        __syncthreads();   // protect hs reuse next step (R2-proven skeleton)
    }
}

// ---------------- BatchNorm statistics over T per feature ----------------
__global__ __launch_bounds__(256) void k_bnstats() {
    __shared__ float ssum[256], ssq[256];
    const int f  = blockIdx.x * 32 + (threadIdx.x & 31);
    const int ty = threadIdx.x >> 5;
    float s = 0.f, q = 0.f;
    for (int t = ty; t < T_SEQ; t += 8) {
        float v = g_h2[(size_t)t * H_DIM + f];
        s += v; q = fmaf(v, v, q);
    }
    ssum[threadIdx.x] = s; ssq[threadIdx.x] = q;
    __syncthreads();
    if (ty == 0) {
#pragma unroll
        for (int k = 1; k < 8; k++) { s += ssum[threadIdx.x + 32 * k]; q += ssq[threadIdx.x + 32 * k]; }
        float mu  = s * (1.f / T_SEQ);
        float var = q * (1.f / T_SEQ) - mu * mu;
        g_mu[f] = mu;
        g_rs[f] = rsqrtf(var + 1e-5f);
    }
}

// ---------------- fold BN + fc into per-feature coefficient + scalar offset ----------------
__global__ __launch_bounds__(256) void k_coeff(const float* __restrict__ gamma,
                                               const float* __restrict__ beta,
                                               const float* __restrict__ fcw,
                                               const float* __restrict__ fcb) {
    __shared__ float red[256];
    float part = 0.f;
    for (int j = threadIdx.x; j < H_DIM; j += 256) {
        float rs = g_rs[j];
        float c = gamma[j] * rs * fcw[j];
        g_c[j] = c;
        part += beta[j] * fcw[j] - g_mu[j] * c;
    }
    red[threadIdx.x] = part;
    __syncthreads();
    for (int k = 128; k > 0; k >>= 1) {
        if (threadIdx.x < k) red[threadIdx.x] += red[threadIdx.x + k];
        __syncthreads();
    }
    if (threadIdx.x == 0) g_off[0] = fcb[0] + red[0];
}

// ---------------- head: y[t] = dot(h2[t], c) + off ----------------
__global__ __launch_bounds__(256) void k_head(float* __restrict__ y) {
    __shared__ float cs[H_DIM];
    for (int i = threadIdx.x; i < H_DIM; i += 256) cs[i] = g_c[i];
    __syncthreads();
    const int warp = threadIdx.x >> 5, lane = threadIdx.x & 31;
    const int t = blockIdx.x * 8 + warp;
    const float* row = g_h2 + (size_t)t * H_DIM;
    float s = 0.f;
#pragma unroll
    for (int k = 0; k < 32; k++) s = fmaf(row[lane + 32 * k], cs[lane + 32 * k], s);
#pragma unroll
    for (int off = 16; off > 0; off >>= 1) s += __shfl_xor_sync(0xffffffffu, s, off);
    if (lane == 0) y[t] = s + g_off[0];
}

// ---------------- launch ----------------
extern "C" void kernel_launch(void* const* d_in, const int* in_sizes, int n_in,
                              void* d_out, int out_size) {
    const float* x     = (const float*)d_in[0];
    const float* w_ih0 = (const float*)d_in[1];
    const float* w_hh0 = (const float*)d_in[2];
    const float* b_ih0 = (const float*)d_in[3];
    const float* b_hh0 = (const float*)d_in[4];
    const float* w_ih1 = (const float*)d_in[5];
    const float* w_hh1 = (const float*)d_in[6];
    const float* b_ih1 = (const float*)d_in[7];
    const float* b_hh1 = (const float*)d_in[8];
    const float* gamma = (const float*)d_in[9];
    const float* beta  = (const float*)d_in[10];
    const float* fcw   = (const float*)d_in[11];
    const float* fcb   = (const float*)d_in[12];
    float* y = (float*)d_out;

    dim3 ggrid(G3 / 128, T_SEQ / 128);

    float* h1;
    cudaGetSymbolAddress((void**)&h1, g_h1);
    float* h2;
    cudaGetSymbolAddress((void**)&h2, g_h2);

    // layer 0
    k_init<<<8, 256>>>();
    k_gemm<IN_DIM, 0><<<ggrid, 256>>>(x, w_ih0, b_ih0);
    k_gru<<<128, 256>>>(w_hh0, b_hh0, h1);
    // layer 1
    k_init<<<8, 256>>>();
    k_gemm<H_DIM, 1><<<ggrid, 256>>>(nullptr, w_ih1, b_ih1);
    k_gru<<<128, 256>>>(w_hh1, b_hh1, h2);
    // BN + head
    k_bnstats<<<32, 256>>>();
    k_coeff<<<1, 256>>>(gamma, beta, fcw, fcb);
    k_head<<<T_SEQ / 8, 256>>>(y);
}

// round 7
// speedup vs baseline: 3.5223x; 3.5223x over previous
#include <cuda_runtime.h>
#include <cstdint>

#define T_SEQ 16384
#define IN_DIM 512
#define H_DIM  1024
#define G3     3072   // 3*H
#define NCTA   128

// ---------------- scratch (static __device__, no allocations) ----------------
__device__ float g_gx[(size_t)T_SEQ * G3];          // 192 MiB, reused for both layers
__device__ float g_h1[(size_t)T_SEQ * H_DIM];       // 64 MiB
__device__ float g_h2[(size_t)T_SEQ * H_DIM];       // 64 MiB
__device__ float g_hx[2][H_DIM];                    // h exchange (parity double-buffered, plain f32)
__device__ unsigned g_cnt[2];                       // per-parity arrival counters (monotonic)
__device__ float g_mu[H_DIM];
__device__ float g_rs[H_DIM];                       // rsqrt(var+eps)
__device__ float g_c[H_DIM];                        // fused BN*fc coefficient
__device__ float g_off[1];

// packed f32x2 FMA: d = a*b + d (per 32-bit half). Only reachable via PTX.
__device__ __forceinline__ void ffma2(unsigned long long& d,
                                      unsigned long long a,
                                      unsigned long long b) {
    asm("fma.rn.f32x2 %0, %1, %2, %0;" : "+l"(d) : "l"(a), "l"(b));
}
__device__ __forceinline__ float hsum2(unsigned long long v) {
    float2 f = *reinterpret_cast<float2*>(&v);
    return f.x + f.y;
}

// ---------------- init: reset exchange state (per launch, graph-replay safe) ----
__global__ void k_init() {
    int i = blockIdx.x * blockDim.x + threadIdx.x;
    if (i < 2 * H_DIM) ((float*)g_hx)[i] = 0.f;
    if (i == 0) {
        g_cnt[0] = NCTA;   // parity-0 buffer pre-armed with h_0 = 0
        g_cnt[1] = 0;
    }
}

// ---------------- GEMM: C[M,3072] = A[M,K] @ W[3072,K]^T + bias ----------------
template<int K, int LAYER>
__global__ __launch_bounds__(256) void k_gemm(const float* __restrict__ Ain,
                                              const float* __restrict__ W,
                                              const float* __restrict__ bias) {
    const float* A = (LAYER == 0) ? Ain : g_h1;
    float* C = g_gx;
    __shared__ float As[16][128];
    __shared__ float Bs[16][128];
    const int tid = threadIdx.x;
    const int bm = blockIdx.y * 128;
    const int bn = blockIdx.x * 128;
    const int tx = tid & 15, ty = tid >> 4;

    float acc[8][8];
#pragma unroll
    for (int i = 0; i < 8; i++)
#pragma unroll
        for (int j = 0; j < 8; j++) acc[i][j] = 0.f;

    for (int k0 = 0; k0 < K; k0 += 16) {
#pragma unroll
        for (int i = 0; i < 2; i++) {
            int f = tid + i * 256;
            int m = f >> 2;
            int kq = (f & 3) << 2;
            float4 va = *(const float4*)(A + (size_t)(bm + m) * K + k0 + kq);
            As[kq + 0][m] = va.x; As[kq + 1][m] = va.y;
            As[kq + 2][m] = va.z; As[kq + 3][m] = va.w;
            float4 vb = *(const float4*)(W + (size_t)(bn + m) * K + k0 + kq);
            Bs[kq + 0][m] = vb.x; Bs[kq + 1][m] = vb.y;
            Bs[kq + 2][m] = vb.z; Bs[kq + 3][m] = vb.w;
        }
        __syncthreads();
#pragma unroll
        for (int kk = 0; kk < 16; kk++) {
            float a[8], b[8];
            *(float4*)(a)     = *(const float4*)&As[kk][ty * 8];
            *(float4*)(a + 4) = *(const float4*)&As[kk][ty * 8 + 4];
            *(float4*)(b)     = *(const float4*)&Bs[kk][tx * 8];
            *(float4*)(b + 4) = *(const float4*)&Bs[kk][tx * 8 + 4];
#pragma unroll
            for (int i = 0; i < 8; i++)
#pragma unroll
                for (int j = 0; j < 8; j++)
                    acc[i][j] = fmaf(a[i], b[j], acc[i][j]);
        }
        __syncthreads();
    }
#pragma unroll
    for (int i = 0; i < 8; i++) {
        int m = bm + ty * 8 + i;
#pragma unroll
        for (int j = 0; j < 8; j += 4) {
            int n = bn + tx * 8 + j;
            float4 o;
            o.x = acc[i][j + 0] + bias[n + 0];
            o.y = acc[i][j + 1] + bias[n + 1];
            o.z = acc[i][j + 2] + bias[n + 2];
            o.w = acc[i][j + 3] + bias[n + 3];
            *(float4*)(C + (size_t)m * G3 + n) = o;
        }
    }
}

// ---------------- persistent GRU recurrence ----------------
// Counter-based handshake: readiness = one gpu-scope counter per parity;
// data = plain f32 buffer, bulk-loaded ONCE per step (no spinning on data).
//   producer (per CTA): 8 lane-0 st.relaxed.gpu.f32 -> __syncthreads ->
//                       thread0 red.release.gpu.add(cnt[par^1], 1)
//   consumer: thread0 ld.acquire.gpu poll (single word, 128 pollers total) ->
//             __syncthreads -> all threads 2x ld.relaxed.gpu.b64 burst -> STS
// Counters are monotonic (target 128*((t>>1)+1)); parity-0 pre-armed for h_0.
// Overwrite safety: h_{t+1} can be published only after every CTA consumed
// h_{t-1} (it must have finished step t-1 to publish h_t, needed for cnt).
__global__ __launch_bounds__(256, 1) void k_gru(const float* __restrict__ w_hh,
                                                const float* __restrict__ b_hh,
                                                float* __restrict__ h_out) {
    __shared__ float hs[H_DIM];
    const int tid  = threadIdx.x;
    const int warp = tid >> 5;
    const int lane = tid & 31;
    const int j = blockIdx.x * 8 + warp;

    // Packed recurrent weights: wX2[k] = {w[2*lane+64k], w[2*lane+64k+1]}
    unsigned long long wr2[16], wz2[16], wn2[16];
    {
        const float* pr = w_hh + (size_t)j * H_DIM + 2 * lane;
        const float* pz = w_hh + (size_t)(H_DIM + j) * H_DIM + 2 * lane;
        const float* pn = w_hh + (size_t)(2 * H_DIM + j) * H_DIM + 2 * lane;
#pragma unroll
        for (int k = 0; k < 16; k++) {
            wr2[k] = *(const unsigned long long*)(pr + 64 * k);
            wz2[k] = *(const unsigned long long*)(pz + 64 * k);
            wn2[k] = *(const unsigned long long*)(pn + 64 * k);
        }
    }
    float bhr = 0.f, bhz = 0.f, bhn = 0.f;
    float gxr = 0.f, gxz = 0.f, gxn = 0.f;
    if (lane == 0) {
        bhr = b_hh[j]; bhz = b_hh[H_DIM + j]; bhn = b_hh[2 * H_DIM + j];
        gxr = __ldg(&g_gx[j]);
        gxz = __ldg(&g_gx[H_DIM + j]);
        gxn = __ldg(&g_gx[2 * H_DIM + j]);
    }

    for (int t = 0; t < T_SEQ; t++) {
        const int par = t & 1;

        // ---- readiness: thread0 polls the parity counter (acquire) ----
        if (tid == 0) {
            const unsigned target = (unsigned)NCTA * ((unsigned)(t >> 1) + 1u);
            unsigned c;
            do {
                asm volatile("ld.acquire.gpu.u32 %0, [%1];"
                             : "=r"(c) : "l"(&g_cnt[par]) : "memory");
            } while (c < target);
        }
        __syncthreads();

        // ---- bulk load h(t): one burst, 16B/thread via 2x strong b64 ----
        {
            const unsigned long long* src = (const unsigned long long*)g_hx[par] + tid * 2;
            unsigned long long u0, u1;
            asm volatile("ld.relaxed.gpu.b64 %0, [%1];" : "=l"(u0) : "l"(src + 0) : "memory");
            asm volatile("ld.relaxed.gpu.b64 %0, [%1];" : "=l"(u1) : "l"(src + 1) : "memory");
            ((unsigned long long*)hs)[tid * 2 + 0] = u0;
            ((unsigned long long*)hs)[tid * 2 + 1] = u1;
        }
        __syncthreads();

        // ---- packed dot products: 16 float2 per gate per lane ----
        unsigned long long aR2 = 0ull, aZ2 = 0ull, aN2 = 0ull;
        const unsigned long long* hp = (const unsigned long long*)hs;
#pragma unroll
        for (int k = 0; k < 16; k++) {
            unsigned long long h2 = hp[lane + 32 * k];
            ffma2(aR2, wr2[k], h2);
            ffma2(aZ2, wz2[k], h2);
            ffma2(aN2, wn2[k], h2);
        }
        float aR = hsum2(aR2), aZ = hsum2(aZ2), aN = hsum2(aN2);
#pragma unroll
        for (int off = 16; off > 0; off >>= 1) {
            aR += __shfl_xor_sync(0xffffffffu, aR, off);
            aZ += __shfl_xor_sync(0xffffffffu, aZ, off);
            aN += __shfl_xor_sync(0xffffffffu, aN, off);
        }

        if (lane == 0) {
            float r = 1.f / (1.f + __expf(-(gxr + aR + bhr)));
            float z = 1.f / (1.f + __expf(-(gxz + aZ + bhz)));
            float npre = gxn + r * (aN + bhn);
            npre = fminf(fmaxf(npre, -20.f), 20.f);
            float e = __expf(-2.f * npre);
            float n = (1.f - e) / (1.f + e);
            float hprev = hs[j];
            float hnew = (1.f - z) * n + z * hprev;

            // publish h(t+1) value (relaxed; ordered by the release below)
            asm volatile("st.relaxed.gpu.f32 [%0], %1;"
                         :: "l"(&g_hx[par ^ 1][j]), "f"(hnew) : "memory");

            h_out[(size_t)t * H_DIM + j] = hnew;

            int tn = (t + 1 < T_SEQ) ? (t + 1) : t;
            const float* gp = g_gx + (size_t)tn * G3;
            gxr = __ldg(gp + j);
            gxz = __ldg(gp + H_DIM + j);
            gxn = __ldg(gp + 2 * H_DIM + j);
        }
        __syncthreads();   // all 8 publishes of this CTA done

        if (tid == 0) {
            // release: makes this CTA's publishes visible before the count
            asm volatile("red.release.gpu.global.add.u32 [%0], %1;"
                         :: "l"(&g_cnt[par ^ 1]), "r"(1u) : "memory");
        }
    }
}

// ---------------- BatchNorm statistics over T per feature ----------------
__global__ __launch_bounds__(256) void k_bnstats() {
    __shared__ float ssum[256], ssq[256];
    const int f  = blockIdx.x * 32 + (threadIdx.x & 31);
    const int ty = threadIdx.x >> 5;
    float s = 0.f, q = 0.f;
    for (int t = ty; t < T_SEQ; t += 8) {
        float v = g_h2[(size_t)t * H_DIM + f];
        s += v; q = fmaf(v, v, q);
    }
    ssum[threadIdx.x] = s; ssq[threadIdx.x] = q;
    __syncthreads();
    if (ty == 0) {
#pragma unroll
        for (int k = 1; k < 8; k++) { s += ssum[threadIdx.x + 32 * k]; q += ssq[threadIdx.x + 32 * k]; }
        float mu  = s * (1.f / T_SEQ);
        float var = q * (1.f / T_SEQ) - mu * mu;
        g_mu[f] = mu;
        g_rs[f] = rsqrtf(var + 1e-5f);
    }
}

// ---------------- fold BN + fc into per-feature coefficient + scalar offset ----------------
__global__ __launch_bounds__(256) void k_coeff(const float* __restrict__ gamma,
                                               const float* __restrict__ beta,
                                               const float* __restrict__ fcw,
                                               const float* __restrict__ fcb) {
    __shared__ float red[256];
    float part = 0.f;
    for (int j = threadIdx.x; j < H_DIM; j += 256) {
        float rs = g_rs[j];
        float c = gamma[j] * rs * fcw[j];
        g_c[j] = c;
        part += beta[j] * fcw[j] - g_mu[j] * c;
    }
    red[threadIdx.x] = part;
    __syncthreads();
    for (int k = 128; k > 0; k >>= 1) {
        if (threadIdx.x < k) red[threadIdx.x] += red[threadIdx.x + k];
        __syncthreads();
    }
    if (threadIdx.x == 0) g_off[0] = fcb[0] + red[0];
}

// ---------------- head: y[t] = dot(h2[t], c) + off ----------------
__global__ __launch_bounds__(256) void k_head(float* __restrict__ y) {
    __shared__ float cs[H_DIM];
    for (int i = threadIdx.x; i < H_DIM; i += 256) cs[i] = g_c[i];
    __syncthreads();
    const int warp = threadIdx.x >> 5, lane = threadIdx.x & 31;
    const int t = blockIdx.x * 8 + warp;
    const float* row = g_h2 + (size_t)t * H_DIM;
    float s = 0.f;
#pragma unroll
    for (int k = 0; k < 32; k++) s = fmaf(row[lane + 32 * k], cs[lane + 32 * k], s);
#pragma unroll
    for (int off = 16; off > 0; off >>= 1) s += __shfl_xor_sync(0xffffffffu, s, off);
    if (lane == 0) y[t] = s + g_off[0];
}

// ---------------- launch ----------------
extern "C" void kernel_launch(void* const* d_in, const int* in_sizes, int n_in,
                              void* d_out, int out_size) {
    const float* x     = (const float*)d_in[0];
    const float* w_ih0 = (const float*)d_in[1];
    const float* w_hh0 = (const float*)d_in[2];
    const float* b_ih0 = (const float*)d_in[3];
    const float* b_hh0 = (const float*)d_in[4];
    const float* w_ih1 = (const float*)d_in[5];
    const float* w_hh1 = (const float*)d_in[6];
    const float* b_ih1 = (const float*)d_in[7];
    const float* b_hh1 = (const float*)d_in[8];
    const float* gamma = (const float*)d_in[9];
    const float* beta  = (const float*)d_in[10];
    const float* fcw   = (const float*)d_in[11];
    const float* fcb   = (const float*)d_in[12];
    float* y = (float*)d_out;

    dim3 ggrid(G3 / 128, T_SEQ / 128);

    float* h1;
    cudaGetSymbolAddress((void**)&h1, g_h1);
    float* h2;
    cudaGetSymbolAddress((void**)&h2, g_h2);

    // layer 0
    k_init<<<8, 256>>>();
    k_gemm<IN_DIM, 0><<<ggrid, 256>>>(x, w_ih0, b_ih0);
    k_gru<<<NCTA, 256>>>(w_hh0, b_hh0, h1);
    // layer 1
    k_init<<<8, 256>>>();
    k_gemm<H_DIM, 1><<<ggrid, 256>>>(nullptr, w_ih1, b_ih1);
    k_gru<<<NCTA, 256>>>(w_hh1, b_hh1, h2);
    // BN + head
    k_bnstats<<<32, 256>>>();
    k_coeff<<<1, 256>>>(gamma, beta, fcw, fcb);
    k_head<<<T_SEQ / 8, 256>>>(y);
}